// round 11
// baseline (speedup 1.0000x reference)
#include <cuda_runtime.h>

// Problem constants (fixed by setup_inputs): B=64, T=8000, M=80
#define B_   64
#define T_   8000
#define M_   80
#define TC   80                  // timesteps per block-chunk (contiguous 25.6KB)
#define SUBS 4                   // time-subchunks per chunk
#define TSUB (TC / SUBS)         // 20 timesteps per thread
#define NC   (T_ / TC)           // 100 chunks
#define THREADS 320              // 80 mels x 4 subchunks
#define EPS 1e-6f
#define SENTINEL 0xFFFFFFFFu     // -NaN bits; published values are finite -> no collision
#define CSTRIDE (B_ * M_)        // slot stride between consecutive chunks
#define LBATCH 4                 // lookback walk MLP batch
#define CHUNK_FLOATS (TC * M_)   // 6400
#define CHUNK_VEC4   (CHUNK_FLOATS / 4)

// Per-(chunk,b,m) slot: low 32 = local endpoint, high 32 = inclusive endpoint.
__device__ unsigned long long g_slot[NC * B_ * M_];   // 4.1 MB
__device__ float4 g_pow[M_];   // (-alpha, r, delta, delta^r)
__device__ float4 g_ema[M_];   // (s, 1-s, (1-s)^TSUB, (1-s)^TC)

__device__ __forceinline__ float fast_log2(float x) {
    float y; asm("lg2.approx.f32 %0, %1;" : "=f"(y) : "f"(x)); return y;
}
__device__ __forceinline__ float fast_exp2(float x) {
    float y; asm("ex2.approx.f32 %0, %1;" : "=f"(y) : "f"(x)); return y;
}
__device__ __forceinline__ unsigned long long ld_relaxed64(const unsigned long long* p) {
    unsigned long long v;
    asm volatile("ld.relaxed.gpu.b64 %0, [%1];" : "=l"(v) : "l"(p) : "memory");
    return v;
}
__device__ __forceinline__ void st_release64(unsigned long long* p, unsigned long long v) {
    asm volatile("st.release.gpu.b64 [%0], %1;" :: "l"(p), "l"(v) : "memory");
}
__device__ __forceinline__ void st_stream(float* p, float v) {
    asm volatile("st.global.cs.f32 [%0], %1;" :: "l"(p), "f"(v) : "memory");
}

// Init: sentinel-fill slots (grid-strided) + per-mel params (block 0).
__global__ void pcen_init_kernel(const float* __restrict__ log_s,
                                 const float* __restrict__ log_alpha,
                                 const float* __restrict__ log_delta,
                                 const float* __restrict__ log_r)
{
    const int i = blockIdx.x * blockDim.x + threadIdx.x;
    if (i < NC * B_ * M_) g_slot[i] = ~0ULL;
    if (blockIdx.x == 0 && threadIdx.x < M_) {
        const int m = threadIdx.x;
        const float s     = expf(log_s[m]);
        const float om    = 1.0f - s;
        const float alpha = expf(log_alpha[m]);
        const float delta = expf(log_delta[m]);
        const float r     = expf(log_r[m]);
        g_pow[m] = make_float4(-alpha, r, delta, powf(delta, r));
        g_ema[m] = make_float4(s, om, powf(om, (float)TSUB), powf(om, (float)TC));
    }
}

extern __shared__ float smem[];
// layout: s_x[6400] | s_l[320] (sub-scan endpoints) | s_c[80] (resolved carries)

__global__ __launch_bounds__(THREADS, 6)
void pcen_block_kernel(const float* __restrict__ x, float* __restrict__ out)
{
    float* const s_x = smem;
    float* const s_l = smem + CHUNK_FLOATS;
    float* const s_c = s_l + THREADS;

    const int tid = threadIdx.x;
    const int bid = blockIdx.x;
    const int b   = bid % B_;
    const int c   = bid / B_;          // chunk-major: predecessors scheduled first
    const int m   = tid % M_;
    const int sub = tid / M_;          // 0..3
    const int base = (b * T_ + c * TC) * M_;   // contiguous 6400-float chunk
    const int bm   = b * M_ + m;

    const float4 E = g_ema[m];   // s, om, om^TSUB, om^TC
    const float4 P = g_pow[m];   // -alpha, r, delta, delta^r
    const float s = E.x, om = E.y, omts = E.z, powTc = E.w;

    // ---- stage the whole chunk DRAM->SMEM with 16B cp.async (max MLP, 0 regs) ----
    {
        const float4* src = (const float4*)(x + base);
        const unsigned sb = (unsigned)__cvta_generic_to_shared(s_x);
        #pragma unroll
        for (int i = 0; i < CHUNK_VEC4 / THREADS; ++i) {
            const int idx = tid + i * THREADS;
            asm volatile("cp.async.ca.shared.global [%0], [%1], 16;"
                         :: "r"(sb + 16u * idx), "l"(src + idx) : "memory");
        }
        asm volatile("cp.async.commit_group;" ::: "memory");
    }

    // ---- carry resolution: depends ONLY on predecessor slots -> overlaps DRAM stage ----
    if (sub == 0) {
        float carry = 0.f;
        if (c > 0) {
            unsigned long long v0 = ld_relaxed64(&g_slot[(c - 1) * CSTRIDE + bm]);
            if ((unsigned)(v0 >> 32) != SENTINEL) {
                carry = __uint_as_float((unsigned)(v0 >> 32));   // fast path: probe hit
            } else {
                float acc = 0.f, w = 1.f;
                int j = c - 1;
                bool done = false;
                while (!done) {
                    unsigned long long v[LBATCH];
                    const int n = (j + 1 < LBATCH) ? (j + 1) : LBATCH;
                    #pragma unroll
                    for (int k2 = 0; k2 < LBATCH; ++k2)          // independent L2 loads
                        if (k2 < n) v[k2] = ld_relaxed64(&g_slot[(j - k2) * CSTRIDE + bm]);
                    for (int k2 = 0; k2 < n; ++k2) {             // consume j, j-1, ...
                        const int jj = j - k2;
                        unsigned long long pv = v[k2];
                        unsigned lo = (unsigned)pv, hi = (unsigned)(pv >> 32);
                        while (lo == SENTINEL) {                 // poll until local appears
                            __nanosleep(32);
                            pv = ld_relaxed64(&g_slot[jj * CSTRIDE + bm]);
                            lo = (unsigned)pv; hi = (unsigned)(pv >> 32);
                        }
                        if (hi != SENTINEL) {                    // inclusive -> terminate
                            carry = fmaf(w, __uint_as_float(hi), acc);
                            done = true;
                            break;
                        }
                        acc = fmaf(w, __uint_as_float(lo), acc);
                        w  *= powTc;
                    }
                    if (!done) { j -= n; if (j < 0) { carry = acc; done = true; } }
                }
            }
        }
        s_c[m] = carry;                // visible to all after the barrier below
    }

    asm volatile("cp.async.wait_group 0;" ::: "memory");
    __syncthreads();

    // ---- sub-scan: each thread scans its 20 timesteps (s factored out) ----
    float l = 0.f;
    const int t0 = sub * TSUB;
    {
        const float* px = s_x + t0 * M_ + m;
        #pragma unroll
        for (int k = 0; k < TSUB; ++k)
            l = fmaf(om, l, px[k * M_]);
        l *= s;                        // l = s * sum om^{...} x
    }
    s_l[tid] = l;
    __syncthreads();

    // ---- publish {local, inclusive} (sub==0 threads; carry already resolved) ----
    const float carry = s_c[m];
    if (sub == 0) {
        const float L0 = s_l[m], L1 = s_l[M_ + m], L2 = s_l[2 * M_ + m], L3 = s_l[3 * M_ + m];
        const float lend = fmaf(omts, fmaf(omts, fmaf(omts, L0, L1), L2), L3);
        st_release64(&g_slot[c * CSTRIDE + bm],
                     (unsigned long long)__float_as_uint(lend) |
                     ((unsigned long long)__float_as_uint(fmaf(powTc, carry, lend)) << 32));
    }

    // ---- start state for this sub: start = om^TSUB * start_prev + L_prev ----
    float mr = carry;
    #pragma unroll
    for (int j = 0; j < SUBS - 1; ++j)
        if (j < sub) mr = fmaf(omts, mr, s_l[j * M_ + m]);

    // ---- rescan + compress + stream out (all 320 threads, all-SMEM inputs) ----
    {
        const float* px = s_x + t0 * M_ + m;
        float*       po = out + base + t0 * M_ + m;
        #pragma unroll 5
        for (int k = 0; k < TSUB; ++k) {
            const float xv = px[k * M_];
            mr = fmaf(om, mr, s * xv);
            const float vv = xv * fast_exp2(P.x * fast_log2(mr + EPS));  // x*(m+eps)^-alpha
            const float oo = fast_exp2(P.y * fast_log2(vv + P.z)) - P.w; // (v+d)^r - d^r
            st_stream(po + k * M_, oo);                                  // evict-first store
        }
    }
}

extern "C" void kernel_launch(void* const* d_in, const int* in_sizes, int n_in,
                              void* d_out, int out_size)
{
    const float* x  = (const float*)d_in[0];
    const float* ls = (const float*)d_in[1];
    const float* la = (const float*)d_in[2];
    const float* ld = (const float*)d_in[3];
    const float* lr = (const float*)d_in[4];
    float* out = (float*)d_out;

    const int smem_bytes = (CHUNK_FLOATS + THREADS + M_) * (int)sizeof(float);  // ~27.2 KB
    cudaFuncSetAttribute(pcen_block_kernel,
                         cudaFuncAttributeMaxDynamicSharedMemorySize, smem_bytes);

    pcen_init_kernel<<<(NC * B_ * M_ + 255) / 256, 256>>>(ls, la, ld, lr);
    pcen_block_kernel<<<NC * B_, THREADS, smem_bytes>>>(x, out);
}

// round 12
// speedup vs baseline: 2.3931x; 2.3931x over previous
#include <cuda_runtime.h>

// Problem constants (fixed by setup_inputs): B=64, T=8000, M=80
#define B_   64
#define T_   8000
#define M_   80
#define TC   80                  // timesteps per block-chunk (contiguous 25.6KB)
#define SUBS 4                   // time-subchunks per chunk
#define TSUB (TC / SUBS)         // 20 timesteps per thread
#define NC   (T_ / TC)           // 100 chunks
#define THREADS 320              // 80 mels x 4 subchunks
#define EPS 1e-6f
#define SENTINEL 0xFFFFFFFFu     // -NaN bits; published values are finite -> no collision
#define CSTRIDE (B_ * M_)        // slot stride between consecutive chunks
#define LBATCH 4                 // lookback walk MLP batch
#define CHUNK_FLOATS (TC * M_)   // 6400
#define CHUNK_VEC4   (CHUNK_FLOATS / 4)

// Per-(chunk,b,m) slot: low 32 = local endpoint, high 32 = inclusive endpoint.
__device__ unsigned long long g_slot[NC * B_ * M_];   // 4.1 MB
__device__ float4 g_pow[M_];   // (-alpha, r, delta, delta^r)
__device__ float4 g_ema[M_];   // (s, 1-s, (1-s)^TSUB, (1-s)^TC)

__device__ __forceinline__ float fast_log2(float x) {
    float y; asm("lg2.approx.f32 %0, %1;" : "=f"(y) : "f"(x)); return y;
}
__device__ __forceinline__ float fast_exp2(float x) {
    float y; asm("ex2.approx.f32 %0, %1;" : "=f"(y) : "f"(x)); return y;
}
__device__ __forceinline__ unsigned long long ld_relaxed64(const unsigned long long* p) {
    unsigned long long v;
    asm volatile("ld.relaxed.gpu.b64 %0, [%1];" : "=l"(v) : "l"(p) : "memory");
    return v;
}
__device__ __forceinline__ void st_release64(unsigned long long* p, unsigned long long v) {
    asm volatile("st.release.gpu.b64 [%0], %1;" :: "l"(p), "l"(v) : "memory");
}
__device__ __forceinline__ void st_stream(float* p, float v) {
    asm volatile("st.global.cs.f32 [%0], %1;" :: "l"(p), "f"(v) : "memory");
}

// Init: sentinel-fill slots + per-mel params (block 0).
__global__ void pcen_init_kernel(const float* __restrict__ log_s,
                                 const float* __restrict__ log_alpha,
                                 const float* __restrict__ log_delta,
                                 const float* __restrict__ log_r)
{
    const int i = blockIdx.x * blockDim.x + threadIdx.x;
    if (i < NC * B_ * M_) g_slot[i] = ~0ULL;
    if (blockIdx.x == 0 && threadIdx.x < M_) {
        const int m = threadIdx.x;
        const float s     = expf(log_s[m]);
        const float om    = 1.0f - s;
        const float alpha = expf(log_alpha[m]);
        const float delta = expf(log_delta[m]);
        const float r     = expf(log_r[m]);
        g_pow[m] = make_float4(-alpha, r, delta, powf(delta, r));
        g_ema[m] = make_float4(s, om, powf(om, (float)TSUB), powf(om, (float)TC));
    }
}

extern __shared__ float smem[];
// layout: s_x[6400] | s_l[320] (sub-scan endpoints) | s_c[80] (resolved carries)

__global__ __launch_bounds__(THREADS, 6)
void pcen_block_kernel(const float* __restrict__ x, float* __restrict__ out)
{
    float* const s_x = smem;
    float* const s_l = smem + CHUNK_FLOATS;
    float* const s_c = s_l + THREADS;

    const int tid = threadIdx.x;
    const int bid = blockIdx.x;
    const int b   = bid % B_;
    const int c   = bid / B_;          // chunk-major: predecessors scheduled first
    const int m   = tid % M_;
    const int sub = tid / M_;          // 0..3
    const int base = (b * T_ + c * TC) * M_;   // contiguous 6400-float chunk
    const int bm   = b * M_ + m;

    const float4 E = g_ema[m];   // s, om, om^TSUB, om^TC
    const float4 P = g_pow[m];   // -alpha, r, delta, delta^r
    const float s = E.x, om = E.y, omts = E.z, powTc = E.w;

    // ---- stage the whole chunk DRAM->SMEM with 16B cp.async (max MLP, 0 regs) ----
    {
        const float4* src = (const float4*)(x + base);
        const unsigned sb = (unsigned)__cvta_generic_to_shared(s_x);
        #pragma unroll
        for (int i = 0; i < CHUNK_VEC4 / THREADS; ++i) {
            const int idx = tid + i * THREADS;
            asm volatile("cp.async.ca.shared.global [%0], [%1], 16;"
                         :: "r"(sb + 16u * idx), "l"(src + idx) : "memory");
        }
        asm volatile("cp.async.commit_group;" ::: "memory");
    }

    // ---- probe-only prefetch of predecessor inclusive: NO SPIN here (a spin
    //      upstream of our own local publication would re-serialize the chain) ----
    unsigned long long v0 = 0;
    if (sub == 0 && c > 0) v0 = ld_relaxed64(&g_slot[(c - 1) * CSTRIDE + bm]);

    asm volatile("cp.async.wait_group 0;" ::: "memory");
    __syncthreads();

    // ---- sub-scan: each thread scans its 20 timesteps (s factored out) ----
    float l = 0.f;
    const int t0 = sub * TSUB;
    {
        const float* px = s_x + t0 * M_ + m;
        #pragma unroll
        for (int k = 0; k < TSUB; ++k)
            l = fmaf(om, l, px[k * M_]);
        l *= s;                        // l = s * sum om^{...} x
    }
    s_l[tid] = l;
    __syncthreads();

    // ---- sub==0: publish local FIRST, then resolve carry, then publish inclusive ----
    if (sub == 0) {
        const float L0 = s_l[m], L1 = s_l[M_ + m], L2 = s_l[2 * M_ + m], L3 = s_l[3 * M_ + m];
        const float lend = fmaf(omts, fmaf(omts, fmaf(omts, L0, L1), L2), L3);
        const unsigned lb = __float_as_uint(lend);
        unsigned long long* const slot = &g_slot[c * CSTRIDE + bm];

        float carry = 0.f;
        if (c > 0) {
            if ((unsigned)(v0 >> 32) != SENTINEL) {
                carry = __uint_as_float((unsigned)(v0 >> 32));   // prefetch hit: free carry
            } else {
                // publish local BEFORE any spin: successors can always make progress
                st_release64(slot, (unsigned long long)lb | ((unsigned long long)SENTINEL << 32));
                float acc = 0.f, w = 1.f;
                int j = c - 1;
                bool done = false;
                while (!done) {
                    unsigned long long v[LBATCH];
                    const int n = (j + 1 < LBATCH) ? (j + 1) : LBATCH;
                    #pragma unroll
                    for (int k2 = 0; k2 < LBATCH; ++k2)          // independent L2 loads
                        if (k2 < n) v[k2] = ld_relaxed64(&g_slot[(j - k2) * CSTRIDE + bm]);
                    for (int k2 = 0; k2 < n; ++k2) {             // consume j, j-1, ...
                        const int jj = j - k2;
                        unsigned long long pv = v[k2];
                        unsigned lo = (unsigned)pv, hi = (unsigned)(pv >> 32);
                        while (lo == SENTINEL) {                 // poll until local appears
                            __nanosleep(32);
                            pv = ld_relaxed64(&g_slot[jj * CSTRIDE + bm]);
                            lo = (unsigned)pv; hi = (unsigned)(pv >> 32);
                        }
                        if (hi != SENTINEL) {                    // inclusive -> terminate
                            carry = fmaf(w, __uint_as_float(hi), acc);
                            done = true;
                            break;
                        }
                        acc = fmaf(w, __uint_as_float(lo), acc);
                        w  *= powTc;
                    }
                    if (!done) { j -= n; if (j < 0) { carry = acc; done = true; } }
                }
            }
        }
        // publish {local, inclusive}
        st_release64(slot, (unsigned long long)lb |
                           ((unsigned long long)__float_as_uint(fmaf(powTc, carry, lend)) << 32));
        s_c[m] = carry;
    }
    __syncthreads();

    // ---- start state for this sub: start = om^TSUB * start_prev + L_prev ----
    float mr = s_c[m];
    #pragma unroll
    for (int j = 0; j < SUBS - 1; ++j)
        if (j < sub) mr = fmaf(omts, mr, s_l[j * M_ + m]);

    // ---- rescan + compress + stream out (all 320 threads, all-SMEM inputs) ----
    {
        const float* px = s_x + t0 * M_ + m;
        float*       po = out + base + t0 * M_ + m;
        #pragma unroll 5
        for (int k = 0; k < TSUB; ++k) {
            const float xv = px[k * M_];
            mr = fmaf(om, mr, s * xv);
            const float vv = xv * fast_exp2(P.x * fast_log2(mr + EPS));  // x*(m+eps)^-alpha
            const float oo = fast_exp2(P.y * fast_log2(vv + P.z)) - P.w; // (v+d)^r - d^r
            st_stream(po + k * M_, oo);                                  // evict-first store
        }
    }
}

extern "C" void kernel_launch(void* const* d_in, const int* in_sizes, int n_in,
                              void* d_out, int out_size)
{
    const float* x  = (const float*)d_in[0];
    const float* ls = (const float*)d_in[1];
    const float* la = (const float*)d_in[2];
    const float* ld = (const float*)d_in[3];
    const float* lr = (const float*)d_in[4];
    float* out = (float*)d_out;

    const int smem_bytes = (CHUNK_FLOATS + THREADS + M_) * (int)sizeof(float);  // ~27.2 KB
    cudaFuncSetAttribute(pcen_block_kernel,
                         cudaFuncAttributeMaxDynamicSharedMemorySize, smem_bytes);

    pcen_init_kernel<<<(NC * B_ * M_ + 255) / 256, 256>>>(ls, la, ld, lr);
    pcen_block_kernel<<<NC * B_, THREADS, smem_bytes>>>(x, out);
}